// round 12
// baseline (speedup 1.0000x reference)
#include <cuda_runtime.h>

// ---------------------------------------------------------------------------
// Routing_2259152797848: capsule routing
// R12 = R10 (best: 268.4us) with k_route at 4 nodes / 512-thread block
//       (named barriers 1-4; inner code per 128-thread group VERBATIM)
//       + k_init folded into k_fc block 0. k_fc scalar (R10 version).
// ---------------------------------------------------------------------------

#define MAXN 50016
#define D    128
#define CH   8
#define KD   16
#define M    32
#define GPB  4              // node groups per block

__device__ float g_z[(size_t)(MAXN + 1) * D];
__device__ int   g_is64;

// --- FC + relu + per-capsule normalize (R10 scalar) + folded init --------------
__global__ void k_fc(const float* __restrict__ x, const float* __restrict__ W,
                     const float* __restrict__ b, const int* __restrict__ nidw,
                     int n) {
    extern __shared__ float smem[];
    float* w_s = smem;             // [128][132]
    float* x_s = smem + 128 * 132; // [32][128]

    const int t = threadIdx.x;
    const int r0 = blockIdx.x * 32;

    // folded init (block 0 only): zero pad row + id-width sniff
    if (blockIdx.x == 0) {
        g_z[(size_t)n * D + t] = 0.0f;
        if (t < 32) {
            int any = 0;
            #pragma unroll
            for (int i = 0; i < 4; i++) any |= nidw[2 * (t * 4 + i) + 1];
            unsigned msk = __ballot_sync(0xffffffffu, any != 0);
            if (t == 0) g_is64 = (msk == 0) ? 1 : 0;
        }
    }

    const float4* W4 = (const float4*)W;
    float4* ws4 = (float4*)w_s;
    #pragma unroll
    for (int i = 0; i < 32; i++) {
        int idx4 = t + 128 * i;
        int j = idx4 >> 5, kk = idx4 & 31;
        ws4[j * 33 + kk] = W4[idx4];
    }
    const float4* X4 = (const float4*)x;
    float4* xs4 = (float4*)x_s;
    #pragma unroll
    for (int i = 0; i < 8; i++) {
        int idx4 = t + 128 * i;
        int r = idx4 >> 5, kk = idx4 & 31;
        float4 v = make_float4(0.f, 0.f, 0.f, 0.f);
        if (r0 + r < n) v = X4[(size_t)(r0 + r) * 32 + kk];
        xs4[r * 32 + kk] = v;
    }
    __syncthreads();

    const int tx = t & 31;
    const int ty = t >> 5;

    float acc[8][4];
    #pragma unroll
    for (int rr = 0; rr < 8; rr++)
        #pragma unroll
        for (int cc = 0; cc < 4; cc++) acc[rr][cc] = 0.f;

    #pragma unroll 4
    for (int k4 = 0; k4 < 32; k4++) {
        float4 wv[4];
        #pragma unroll
        for (int cc = 0; cc < 4; cc++) wv[cc] = ws4[(tx + 32 * cc) * 33 + k4];
        float4 xr[8];
        #pragma unroll
        for (int rr = 0; rr < 8; rr++) xr[rr] = xs4[(ty + 4 * rr) * 32 + k4];
        #pragma unroll
        for (int rr = 0; rr < 8; rr++)
            #pragma unroll
            for (int cc = 0; cc < 4; cc++) {
                acc[rr][cc] = fmaf(xr[rr].x, wv[cc].x, acc[rr][cc]);
                acc[rr][cc] = fmaf(xr[rr].y, wv[cc].y, acc[rr][cc]);
                acc[rr][cc] = fmaf(xr[rr].z, wv[cc].z, acc[rr][cc]);
                acc[rr][cc] = fmaf(xr[rr].w, wv[cc].w, acc[rr][cc]);
            }
    }

    float bv[4];
    #pragma unroll
    for (int cc = 0; cc < 4; cc++) bv[cc] = b[tx + 32 * cc];

    #pragma unroll
    for (int rr = 0; rr < 8; rr++) {
        int row = r0 + ty + 4 * rr;
        #pragma unroll
        for (int cc = 0; cc < 4; cc++) {
            float v = fmaxf(acc[rr][cc] + bv[cc], 0.f);
            float s = v * v;
            s += __shfl_xor_sync(0xffffffffu, s, 1);
            s += __shfl_xor_sync(0xffffffffu, s, 2);
            s += __shfl_xor_sync(0xffffffffu, s, 4);
            s += __shfl_xor_sync(0xffffffffu, s, 8);
            float inv = rsqrtf(fmaxf(s, 1e-24f));
            if (row < n) g_z[(size_t)row * D + tx + 32 * cc] = v * inv;
        }
    }
}

// --- routing: 512 threads = 4 independent nodes (inner code R4 VERBATIM) -------
__global__ __launch_bounds__(512) void k_route(const void* __restrict__ nid_raw,
                                               float* __restrict__ out, int n) {
    __shared__ float d_s[GPB][M * 9];                 // d_s[grp][m*9+c]
    __shared__ __align__(16) float ps[GPB][CH * 36];  // ps[grp][c*36+m]
    __shared__ int ids[GPB][M];

    const int t   = threadIdx.x;
    const int grp = t >> 7;                  // node group 0..3
    const int tl  = t & 127;
    const int bid = 1 + grp;                 // named barrier id (warp-uniform)
    const int node = blockIdx.x * GPB + grp;
    if (node >= n) return;                   // whole 128-group exits together
    const int is64 = g_is64;

    if (tl < M) {
        long long id;
        if (is64) id = ((const long long*)nid_raw)[(size_t)node * M + tl];
        else      id = (long long)((const int*)nid_raw)[(size_t)node * M + tl];
        ids[grp][tl] = (int)id;
    }
    const float xc = g_z[(size_t)node * D + tl];
    asm volatile("bar.sync %0, %1;" :: "r"(bid), "r"(128) : "memory");

    // coalesced gather: one (c,k) column of all 32 neighbor rows
    float nbr[M];
    #pragma unroll
    for (int m = 0; m < M; m++)
        nbr[m] = g_z[(size_t)ids[grp][m] * D + tl];

    const int cB = tl >> 4;          // channel (tree / phase B)
    const int g  = tl & 15;          // lane within 16-lane channel group
    const int m0 = tl >> 3;          // softmax identity
    const int cA = tl & 7;
    const int mbase = ((g & 1) << 4) | ((g & 2) << 2) | (g & 4) | ((g >> 3) << 1);

    float u_val = xc;
    float acc;

    for (int it = 0; it < 3; it++) {
        // ---- tree: d[m] = sum_k u[c,k]*nb[m,c,k], split over 16 lanes ----
        float s1[16];
        #pragma unroll
        for (int i = 0; i < 16; i++) {
            float lo = u_val * nbr[i];
            float hi = u_val * nbr[i + 16];
            float keep = (g & 1) ? hi : lo;
            float send = (g & 1) ? lo : hi;
            s1[i] = keep + __shfl_xor_sync(0xffffffffu, send, 1);
        }
        float s2[8];
        #pragma unroll
        for (int i = 0; i < 8; i++) {
            float keep = (g & 2) ? s1[i + 8] : s1[i];
            float send = (g & 2) ? s1[i] : s1[i + 8];
            s2[i] = keep + __shfl_xor_sync(0xffffffffu, send, 2);
        }
        float s3[4];
        #pragma unroll
        for (int i = 0; i < 4; i++) {
            float keep = (g & 4) ? s2[i + 4] : s2[i];
            float send = (g & 4) ? s2[i] : s2[i + 4];
            s3[i] = keep + __shfl_xor_sync(0xffffffffu, send, 4);
        }
        float s4[2];
        #pragma unroll
        for (int i = 0; i < 2; i++) {
            float keep = (g & 8) ? s3[i + 2] : s3[i];
            float send = (g & 8) ? s3[i] : s3[i + 2];
            s4[i] = keep + __shfl_xor_sync(0xffffffffu, send, 8);
        }
        // |d| <= 1 (unit capsules): exp safe without max-subtraction
        d_s[grp][(mbase + 0) * 9 + cB] = __expf(s4[0]);
        d_s[grp][(mbase + 1) * 9 + cB] = __expf(s4[1]);
        asm volatile("bar.sync %0, %1;" :: "r"(bid), "r"(128) : "memory");

        // ---- softmax over c (8 adjacent lanes), thread = (m0, cA) ----
        float e0 = d_s[grp][m0 * 9 + cA];
        float e1 = d_s[grp][(m0 + 16) * 9 + cA];
        float sm0 = e0, sm1 = e1;
        sm0 += __shfl_xor_sync(0xffffffffu, sm0, 1);
        sm1 += __shfl_xor_sync(0xffffffffu, sm1, 1);
        sm0 += __shfl_xor_sync(0xffffffffu, sm0, 2);
        sm1 += __shfl_xor_sync(0xffffffffu, sm1, 2);
        sm0 += __shfl_xor_sync(0xffffffffu, sm0, 4);
        sm1 += __shfl_xor_sync(0xffffffffu, sm1, 4);
        ps[grp][cA * 36 + m0]      = __fdividef(e0, sm0);
        ps[grp][cA * 36 + m0 + 16] = __fdividef(e1, sm1);
        asm volatile("bar.sync %0, %1;" :: "r"(bid), "r"(128) : "memory");

        // ---- phase B: u[c,k] = x_caps + sum_m p[m,c]*nb[m,c,k] ----
        acc = xc;
        #pragma unroll
        for (int j = 0; j < 8; j++) {
            float4 p = *(const float4*)&ps[grp][cB * 36 + 4 * j];
            acc = fmaf(p.x, nbr[4 * j + 0], acc);
            acc = fmaf(p.y, nbr[4 * j + 1], acc);
            acc = fmaf(p.z, nbr[4 * j + 2], acc);
            acc = fmaf(p.w, nbr[4 * j + 3], acc);
        }

        if (it < 2) {
            float sq = acc * acc;
            sq += __shfl_xor_sync(0xffffffffu, sq, 1);
            sq += __shfl_xor_sync(0xffffffffu, sq, 2);
            sq += __shfl_xor_sync(0xffffffffu, sq, 4);
            sq += __shfl_xor_sync(0xffffffffu, sq, 8);
            u_val = acc * rsqrtf(fmaxf(sq, 1e-24f));
        } else {
            out[(size_t)node * D + tl] = acc;
        }
    }
}

// ---------------------------------------------------------------------------
extern "C" void kernel_launch(void* const* d_in, const int* in_sizes, int n_in,
                              void* d_out, int out_size) {
    const float* x = (const float*)d_in[0];
    const float* W = (const float*)d_in[1];
    const float* b = (const float*)d_in[2];
    const void*  nid = d_in[3];
    float* out = (float*)d_out;

    int n = in_sizes[0] / D;

    static const size_t FC_SMEM = (size_t)(128 * 132 + 32 * 128) * sizeof(float);
    cudaFuncSetAttribute(k_fc, cudaFuncAttributeMaxDynamicSharedMemorySize,
                         (int)FC_SMEM);

    int nblk = (n + 31) / 32;
    k_fc<<<nblk, 128, FC_SMEM>>>(x, W, b, (const int*)nid, n);
    k_route<<<(n + GPB - 1) / GPB, 128 * GPB>>>(nid, out, n);
}

// round 13
// speedup vs baseline: 1.1284x; 1.1284x over previous
#include <cuda_runtime.h>

// ---------------------------------------------------------------------------
// Routing_2259152797848: capsule routing
// R13 = R10 k_route VERBATIM (best total: 268.4us)
//       + k_fc retiled: 64 rows / 256-thread block (16 warps/SM vs 8)
//       + init folded into k_fc block 0.
// ---------------------------------------------------------------------------

#define MAXN 50016
#define D    128
#define CH   8
#define KD   16
#define M    32

__device__ float g_z[(size_t)(MAXN + 1) * D];
__device__ int   g_is64;

// --- FC + relu + per-capsule normalize: 64 rows, 256 threads -------------------
// acc[8][4]: rows ty+8*rr (ty=0..7), cols tx+32*cc. Same per-thread FMA count
// as before (4096), but 16 warps/SM instead of 8 (SMEM 100.4KB -> 2 blocks/SM).
__global__ void k_fc(const float* __restrict__ x, const float* __restrict__ W,
                     const float* __restrict__ b, const int* __restrict__ nidw,
                     int n) {
    extern __shared__ float smem[];
    float* w_s = smem;             // [128][132]
    float* x_s = smem + 128 * 132; // [64][128]

    const int t = threadIdx.x;
    const int r0 = blockIdx.x * 64;

    // folded init (block 0 only): zero pad row + id-width sniff
    if (blockIdx.x == 0) {
        if (t < 128) g_z[(size_t)n * D + t] = 0.0f;
        else if (t < 160) {
            int lane = t - 128;
            int any = 0;
            #pragma unroll
            for (int i = 0; i < 4; i++) any |= nidw[2 * (lane * 4 + i) + 1];
            unsigned msk = __ballot_sync(0xffffffffu, any != 0);
            if (lane == 0) g_is64 = (msk == 0) ? 1 : 0;
        }
    }

    // load W (4096 float4), padded rows of 33 float4
    const float4* W4 = (const float4*)W;
    float4* ws4 = (float4*)w_s;
    #pragma unroll
    for (int i = 0; i < 16; i++) {
        int idx4 = t + 256 * i;
        int j = idx4 >> 5, kk = idx4 & 31;
        ws4[j * 33 + kk] = W4[idx4];
    }
    // load x tile (2048 float4), zero-fill past n
    const float4* X4 = (const float4*)x;
    float4* xs4 = (float4*)x_s;
    #pragma unroll
    for (int i = 0; i < 8; i++) {
        int idx4 = t + 256 * i;
        int r = idx4 >> 5, kk = idx4 & 31;
        float4 v = make_float4(0.f, 0.f, 0.f, 0.f);
        if (r0 + r < n) v = X4[(size_t)(r0 + r) * 32 + kk];
        xs4[r * 32 + kk] = v;
    }
    __syncthreads();

    const int tx = t & 31;   // column lane
    const int ty = t >> 5;   // row group (0..7)

    float acc[8][4];
    #pragma unroll
    for (int rr = 0; rr < 8; rr++)
        #pragma unroll
        for (int cc = 0; cc < 4; cc++) acc[rr][cc] = 0.f;

    #pragma unroll 4
    for (int k4 = 0; k4 < 32; k4++) {
        float4 wv[4];
        #pragma unroll
        for (int cc = 0; cc < 4; cc++) wv[cc] = ws4[(tx + 32 * cc) * 33 + k4];
        float4 xr[8];
        #pragma unroll
        for (int rr = 0; rr < 8; rr++) xr[rr] = xs4[(ty + 8 * rr) * 32 + k4];
        #pragma unroll
        for (int rr = 0; rr < 8; rr++)
            #pragma unroll
            for (int cc = 0; cc < 4; cc++) {
                acc[rr][cc] = fmaf(xr[rr].x, wv[cc].x, acc[rr][cc]);
                acc[rr][cc] = fmaf(xr[rr].y, wv[cc].y, acc[rr][cc]);
                acc[rr][cc] = fmaf(xr[rr].z, wv[cc].z, acc[rr][cc]);
                acc[rr][cc] = fmaf(xr[rr].w, wv[cc].w, acc[rr][cc]);
            }
    }

    float bv[4];
    #pragma unroll
    for (int cc = 0; cc < 4; cc++) bv[cc] = b[tx + 32 * cc];

    // relu + bias + per-capsule (16-col) normalize (16-lane shfl groups)
    #pragma unroll
    for (int rr = 0; rr < 8; rr++) {
        int row = r0 + ty + 8 * rr;
        #pragma unroll
        for (int cc = 0; cc < 4; cc++) {
            float v = fmaxf(acc[rr][cc] + bv[cc], 0.f);
            float s = v * v;
            s += __shfl_xor_sync(0xffffffffu, s, 1);
            s += __shfl_xor_sync(0xffffffffu, s, 2);
            s += __shfl_xor_sync(0xffffffffu, s, 4);
            s += __shfl_xor_sync(0xffffffffu, s, 8);
            float inv = rsqrtf(fmaxf(s, 1e-24f));
            if (row < n) g_z[(size_t)row * D + tx + 32 * cc] = v * inv;
        }
    }
}

// --- routing: 256 threads = 2 independent nodes (R4/R10 VERBATIM) --------------
__global__ __launch_bounds__(256) void k_route(const void* __restrict__ nid_raw,
                                               float* __restrict__ out, int n) {
    __shared__ float d_s[2][M * 9];          // d_s[grp][m*9+c]
    __shared__ __align__(16) float ps[2][CH * 36];  // ps[grp][c*36+m]
    __shared__ int ids[2][M];

    const int t   = threadIdx.x;
    const int grp = t >> 7;                  // node group 0/1
    const int tl  = t & 127;
    const int bid = 1 + grp;                 // named barrier id (warp-uniform)
    const int node = blockIdx.x * 2 + grp;
    if (node >= n) return;                   // whole 128-group exits together
    const int is64 = g_is64;

    if (tl < M) {
        long long id;
        if (is64) id = ((const long long*)nid_raw)[(size_t)node * M + tl];
        else      id = (long long)((const int*)nid_raw)[(size_t)node * M + tl];
        ids[grp][tl] = (int)id;
    }
    const float xc = g_z[(size_t)node * D + tl];
    asm volatile("bar.sync %0, %1;" :: "r"(bid), "r"(128) : "memory");

    // coalesced gather: one (c,k) column of all 32 neighbor rows
    float nbr[M];
    #pragma unroll
    for (int m = 0; m < M; m++)
        nbr[m] = g_z[(size_t)ids[grp][m] * D + tl];

    const int cB = tl >> 4;          // channel (tree / phase B)
    const int g  = tl & 15;          // lane within 16-lane channel group
    const int m0 = tl >> 3;          // softmax identity
    const int cA = tl & 7;
    const int mbase = ((g & 1) << 4) | ((g & 2) << 2) | (g & 4) | ((g >> 3) << 1);

    float u_val = xc;
    float acc;

    for (int it = 0; it < 3; it++) {
        // ---- tree: d[m] = sum_k u[c,k]*nb[m,c,k], split over 16 lanes ----
        float s1[16];
        #pragma unroll
        for (int i = 0; i < 16; i++) {
            float lo = u_val * nbr[i];
            float hi = u_val * nbr[i + 16];
            float keep = (g & 1) ? hi : lo;
            float send = (g & 1) ? lo : hi;
            s1[i] = keep + __shfl_xor_sync(0xffffffffu, send, 1);
        }
        float s2[8];
        #pragma unroll
        for (int i = 0; i < 8; i++) {
            float keep = (g & 2) ? s1[i + 8] : s1[i];
            float send = (g & 2) ? s1[i] : s1[i + 8];
            s2[i] = keep + __shfl_xor_sync(0xffffffffu, send, 2);
        }
        float s3[4];
        #pragma unroll
        for (int i = 0; i < 4; i++) {
            float keep = (g & 4) ? s2[i + 4] : s2[i];
            float send = (g & 4) ? s2[i] : s2[i + 4];
            s3[i] = keep + __shfl_xor_sync(0xffffffffu, send, 4);
        }
        float s4[2];
        #pragma unroll
        for (int i = 0; i < 2; i++) {
            float keep = (g & 8) ? s3[i + 2] : s3[i];
            float send = (g & 8) ? s3[i] : s3[i + 2];
            s4[i] = keep + __shfl_xor_sync(0xffffffffu, send, 8);
        }
        // |d| <= 1 (unit capsules): exp safe without max-subtraction
        d_s[grp][(mbase + 0) * 9 + cB] = __expf(s4[0]);
        d_s[grp][(mbase + 1) * 9 + cB] = __expf(s4[1]);
        asm volatile("bar.sync %0, %1;" :: "r"(bid), "r"(128) : "memory");

        // ---- softmax over c (8 adjacent lanes), thread = (m0, cA) ----
        float e0 = d_s[grp][m0 * 9 + cA];
        float e1 = d_s[grp][(m0 + 16) * 9 + cA];
        float sm0 = e0, sm1 = e1;
        sm0 += __shfl_xor_sync(0xffffffffu, sm0, 1);
        sm1 += __shfl_xor_sync(0xffffffffu, sm1, 1);
        sm0 += __shfl_xor_sync(0xffffffffu, sm0, 2);
        sm1 += __shfl_xor_sync(0xffffffffu, sm1, 2);
        sm0 += __shfl_xor_sync(0xffffffffu, sm0, 4);
        sm1 += __shfl_xor_sync(0xffffffffu, sm1, 4);
        ps[grp][cA * 36 + m0]      = __fdividef(e0, sm0);
        ps[grp][cA * 36 + m0 + 16] = __fdividef(e1, sm1);
        asm volatile("bar.sync %0, %1;" :: "r"(bid), "r"(128) : "memory");

        // ---- phase B: u[c,k] = x_caps + sum_m p[m,c]*nb[m,c,k] ----
        acc = xc;
        #pragma unroll
        for (int j = 0; j < 8; j++) {
            float4 p = *(const float4*)&ps[grp][cB * 36 + 4 * j];
            acc = fmaf(p.x, nbr[4 * j + 0], acc);
            acc = fmaf(p.y, nbr[4 * j + 1], acc);
            acc = fmaf(p.z, nbr[4 * j + 2], acc);
            acc = fmaf(p.w, nbr[4 * j + 3], acc);
        }

        if (it < 2) {
            float sq = acc * acc;
            sq += __shfl_xor_sync(0xffffffffu, sq, 1);
            sq += __shfl_xor_sync(0xffffffffu, sq, 2);
            sq += __shfl_xor_sync(0xffffffffu, sq, 4);
            sq += __shfl_xor_sync(0xffffffffu, sq, 8);
            u_val = acc * rsqrtf(fmaxf(sq, 1e-24f));
        } else {
            out[(size_t)node * D + tl] = acc;
        }
    }
}

// ---------------------------------------------------------------------------
extern "C" void kernel_launch(void* const* d_in, const int* in_sizes, int n_in,
                              void* d_out, int out_size) {
    const float* x = (const float*)d_in[0];
    const float* W = (const float*)d_in[1];
    const float* b = (const float*)d_in[2];
    const void*  nid = d_in[3];
    float* out = (float*)d_out;

    int n = in_sizes[0] / D;

    // W smem [128][132] + x smem [64][128] = 100,352 bytes
    static const size_t FC_SMEM = (size_t)(128 * 132 + 64 * 128) * sizeof(float);
    cudaFuncSetAttribute(k_fc, cudaFuncAttributeMaxDynamicSharedMemorySize,
                         (int)FC_SMEM);

    int nblk = (n + 63) / 64;
    k_fc<<<nblk, 256, FC_SMEM>>>(x, W, b, (const int*)nid, n);
    k_route<<<(n + 1) / 2, 256>>>(nid, out, n);
}